// round 6
// baseline (speedup 1.0000x reference)
#include <cuda_runtime.h>

// Problem constants
#define T_STEPS 256
#define HID     256
#define BATCH   1024
#define LATD    128
#define OUTD    64
#define BC      8      // batch rows per CTA
#define NCTA    (BATCH / BC)  // 128

// -------- persistent scratch (no allocations allowed) --------
// transposed, gate-interleaved weights:
//   g_w0t4[k*256 + j] = (Whh0[j][k], Whh0[j+256][k], Whh0[j+512][k], Whh0[j+768][k])
__device__ float4 g_w0t4[256 * 256];          // 1 MB
// layer1 concatenated [Wih1 ; Whh1], rows k=0..511
__device__ float4 g_w1t4[512 * 256];          // 2 MB
__device__ float  g_wot[256 * 64];            // w_out transposed [k][o]
__device__ float  g_gx0[BATCH * 1024];        // latent@Wih0^T + b_ih0 + b_hh0
__device__ float  g_hinit[BATCH * 512];       // [b][layer*256 + j]
__device__ float  g_cinit[BATCH * 512];

// -------- packed f32x2 helpers (sm_103a FFMA2 path) --------
typedef unsigned long long ull;
__device__ __forceinline__ ull pk2(float a, float b) {
    ull r; asm("mov.b64 %0, {%1, %2};" : "=l"(r) : "f"(a), "f"(b)); return r;
}
__device__ __forceinline__ void upk2(ull v, float& a, float& b) {
    asm("mov.b64 {%0, %1}, %2;" : "=f"(a), "=f"(b) : "l"(v));
}
__device__ __forceinline__ ull dup2f(float a) {
    ull r; asm("mov.b64 %0, {%1, %1};" : "=l"(r) : "f"(a)); return r;
}
__device__ __forceinline__ ull fma2(ull a, ull b, ull c) {
    ull d; asm("fma.rn.f32x2 %0, %1, %2, %3;" : "=l"(d) : "l"(a), "l"(b), "l"(c)); return d;
}

__device__ __forceinline__ float sigf(float x) {
    return __fdividef(1.f, 1.f + __expf(-x));
}
__device__ __forceinline__ float tanh_fast(float x) {
    x = fminf(fmaxf(x, -15.f), 15.f);
    float e = __expf(2.f * x);
    return __fdividef(e - 1.f, e + 1.f);
}

// elementwise LSTM cell update for a packed batch pair
__device__ __forceinline__ void lstm_cell(ull gi, ull gf, ull gg, ull go,
                                          ull& cp, float& ha, float& hb) {
    float ia, ib, fa, fb, ga, gb, oa, ob, ca, cb;
    upk2(gi, ia, ib); upk2(gf, fa, fb); upk2(gg, ga, gb); upk2(go, oa, ob);
    upk2(cp, ca, cb);
    float cna = sigf(fa) * ca + sigf(ia) * tanh_fast(ga);
    float cnb = sigf(fb) * cb + sigf(ib) * tanh_fast(gb);
    ha = sigf(oa) * tanh_fast(cna);
    hb = sigf(ob) * tanh_fast(cnb);
    cp = pk2(cna, cnb);
}

// ================= prep kernels =================

__global__ void tr_w0(const float* __restrict__ w_hh0) {
    int idx = blockIdx.x * blockDim.x + threadIdx.x;   // 65536
    int t = idx & 255, k = idx >> 8;
    g_w0t4[k * 256 + t] = make_float4(
        w_hh0[t * 256 + k],         w_hh0[(t + 256) * 256 + k],
        w_hh0[(t + 512) * 256 + k], w_hh0[(t + 768) * 256 + k]);
}

__global__ void tr_w1(const float* __restrict__ w_ih1, const float* __restrict__ w_hh1) {
    int idx = blockIdx.x * blockDim.x + threadIdx.x;   // 131072
    int t = idx & 255, k = idx >> 8;                   // k in 0..511
    const float* src = (k < 256) ? w_ih1 : w_hh1;
    int kk = k & 255;
    g_w1t4[k * 256 + t] = make_float4(
        src[t * 256 + kk],         src[(t + 256) * 256 + kk],
        src[(t + 512) * 256 + kk], src[(t + 768) * 256 + kk]);
}

__global__ void tr_wo(const float* __restrict__ w_out) {
    int idx = blockIdx.x * blockDim.x + threadIdx.x;   // 16384
    int o = idx & 63, k = idx >> 6;
    g_wot[idx] = w_out[o * 256 + k];
}

// per-batch-row init: gx0, h0/c0 for both layers
__global__ void prep_init(const float* __restrict__ latent,
                          const float* __restrict__ w_lh, const float* __restrict__ b_lh,
                          const float* __restrict__ w_lc, const float* __restrict__ b_lc,
                          const float* __restrict__ w_ih0, const float* __restrict__ b_ih0,
                          const float* __restrict__ b_hh0) {
    __shared__ float lat[LATD];
    const int b = blockIdx.x, t = threadIdx.x;
    if (t < LATD) lat[t] = latent[b * LATD + t];
    __syncthreads();

    // gx0 : 4 gate rows per thread
    #pragma unroll
    for (int g = 0; g < 4; g++) {
        int n = t + 256 * g;
        const float4* wr = (const float4*)(w_ih0 + n * LATD);
        float acc = b_ih0[n] + b_hh0[n];
        #pragma unroll 8
        for (int q = 0; q < LATD / 4; q++) {
            float4 w4 = __ldg(wr + q);
            acc += lat[4 * q] * w4.x + lat[4 * q + 1] * w4.y +
                   lat[4 * q + 2] * w4.z + lat[4 * q + 3] * w4.w;
        }
        g_gx0[b * 1024 + n] = acc;
    }
    // h/c init: j2 in {t, t+256}
    #pragma unroll
    for (int half = 0; half < 2; half++) {
        int j2 = t + 256 * half;
        {
            const float4* wr = (const float4*)(w_lh + j2 * LATD);
            float acc = b_lh[j2];
            #pragma unroll 8
            for (int q = 0; q < LATD / 4; q++) {
                float4 w4 = __ldg(wr + q);
                acc += lat[4 * q] * w4.x + lat[4 * q + 1] * w4.y +
                       lat[4 * q + 2] * w4.z + lat[4 * q + 3] * w4.w;
            }
            g_hinit[b * 512 + j2] = acc;
        }
        {
            const float4* wr = (const float4*)(w_lc + j2 * LATD);
            float acc = b_lc[j2];
            #pragma unroll 8
            for (int q = 0; q < LATD / 4; q++) {
                float4 w4 = __ldg(wr + q);
                acc += lat[4 * q] * w4.x + lat[4 * q + 1] * w4.y +
                       lat[4 * q + 2] * w4.z + lat[4 * q + 3] * w4.w;
            }
            g_cinit[b * 512 + j2] = acc;
        }
    }
}

// ================= main persistent kernel =================
// 128 CTAs x 256 threads. CTA owns 8 batch rows, packed as pairs (bp, bp+4).
// Thread t owns hidden unit j=t of both layers (gate rows t, t+256, t+512, t+768).
// SMEM xp[buf][k][bp]: k<256 -> layer0 h, k>=256 -> layer1 h, packed batch pair.
__global__ void __launch_bounds__(256, 1)
lstm_main(const float* __restrict__ b_ih1, const float* __restrict__ b_hh1,
          const float* __restrict__ b_out, float* __restrict__ out) {
    __shared__ ull xp[2][512][4];
    const int t  = threadIdx.x;
    const int bg = blockIdx.x * BC;

    ull c0p[4], c1p[4], gxp[4][4], b1p[4];
    #pragma unroll
    for (int bp = 0; bp < 4; bp++) {
        int b0 = bg + bp, b1 = bg + bp + 4;
        xp[0][t][bp]       = pk2(g_hinit[b0 * 512 + t],       g_hinit[b1 * 512 + t]);
        xp[0][256 + t][bp] = pk2(g_hinit[b0 * 512 + 256 + t], g_hinit[b1 * 512 + 256 + t]);
        c0p[bp] = pk2(g_cinit[b0 * 512 + t],       g_cinit[b1 * 512 + t]);
        c1p[bp] = pk2(g_cinit[b0 * 512 + 256 + t], g_cinit[b1 * 512 + 256 + t]);
        #pragma unroll
        for (int g = 0; g < 4; g++)
            gxp[g][bp] = pk2(g_gx0[b0 * 1024 + t + 256 * g],
                             g_gx0[b1 * 1024 + t + 256 * g]);
    }
    #pragma unroll
    for (int g = 0; g < 4; g++)
        b1p[g] = dup2f(b_ih1[t + 256 * g] + b_hh1[t + 256 * g]);

    const int oo = t & 63;
    const int rr = t >> 6;
    const ull bop = dup2f(b_out[oo]);

    __syncthreads();

    int cur = 0;
    for (int step = 0; step < T_STEPS; step++) {
        const int nxt = cur ^ 1;

        // ---------- layer 0: gates = gx0 + h0 @ Whh0^T ----------
        ull acc[4][4];
        #pragma unroll
        for (int g = 0; g < 4; g++)
            #pragma unroll
            for (int bp = 0; bp < 4; bp++) acc[g][bp] = gxp[g][bp];

        #pragma unroll 8
        for (int k = 0; k < 256; k++) {
            float4 w = __ldg(&g_w0t4[k * 256 + t]);
            ull wx = dup2f(w.x), wy = dup2f(w.y), wz = dup2f(w.z), ww = dup2f(w.w);
            #pragma unroll
            for (int bp = 0; bp < 4; bp++) {
                ull xv = xp[cur][k][bp];
                acc[0][bp] = fma2(xv, wx, acc[0][bp]);
                acc[1][bp] = fma2(xv, wy, acc[1][bp]);
                acc[2][bp] = fma2(xv, wz, acc[2][bp]);
                acc[3][bp] = fma2(xv, ww, acc[3][bp]);
            }
        }
        #pragma unroll
        for (int bp = 0; bp < 4; bp++) {
            float ha, hb;
            lstm_cell(acc[0][bp], acc[1][bp], acc[2][bp], acc[3][bp], c0p[bp], ha, hb);
            xp[nxt][t][bp] = pk2(ha, hb);
        }
        __syncthreads();   // h0_new visible

        // ---------- layer 1: gates = bias1 + h0_new @ Wih1^T + h1 @ Whh1^T ----------
        #pragma unroll
        for (int g = 0; g < 4; g++)
            #pragma unroll
            for (int bp = 0; bp < 4; bp++) acc[g][bp] = b1p[g];

        #pragma unroll 8
        for (int k = 0; k < 256; k++) {
            float4 w = __ldg(&g_w1t4[k * 256 + t]);
            ull wx = dup2f(w.x), wy = dup2f(w.y), wz = dup2f(w.z), ww = dup2f(w.w);
            #pragma unroll
            for (int bp = 0; bp < 4; bp++) {
                ull xv = xp[nxt][k][bp];          // h0_new
                acc[0][bp] = fma2(xv, wx, acc[0][bp]);
                acc[1][bp] = fma2(xv, wy, acc[1][bp]);
                acc[2][bp] = fma2(xv, wz, acc[2][bp]);
                acc[3][bp] = fma2(xv, ww, acc[3][bp]);
            }
        }
        #pragma unroll 8
        for (int k = 0; k < 256; k++) {
            float4 w = __ldg(&g_w1t4[(256 + k) * 256 + t]);
            ull wx = dup2f(w.x), wy = dup2f(w.y), wz = dup2f(w.z), ww = dup2f(w.w);
            #pragma unroll
            for (int bp = 0; bp < 4; bp++) {
                ull xv = xp[cur][256 + k][bp];    // h1_cur
                acc[0][bp] = fma2(xv, wx, acc[0][bp]);
                acc[1][bp] = fma2(xv, wy, acc[1][bp]);
                acc[2][bp] = fma2(xv, wz, acc[2][bp]);
                acc[3][bp] = fma2(xv, ww, acc[3][bp]);
            }
        }
        #pragma unroll
        for (int bp = 0; bp < 4; bp++) {
            float ha, hb;
            lstm_cell(acc[0][bp], acc[1][bp], acc[2][bp], acc[3][bp], c1p[bp], ha, hb);
            xp[nxt][256 + t][bp] = pk2(ha, hb);
        }
        __syncthreads();   // h1_new visible

        // ---------- output projection: out = h1_new @ Wout^T + b_out ----------
        ull oacc = bop;
        #pragma unroll 8
        for (int k = 0; k < 256; k++) {
            float wv = __ldg(&g_wot[k * 64 + oo]);
            oacc = fma2(xp[nxt][256 + k][rr], dup2f(wv), oacc);
        }
        float va, vb;
        upk2(oacc, va, vb);
        out[((bg + rr) * T_STEPS + step) * OUTD + oo]     = va;
        out[((bg + rr + 4) * T_STEPS + step) * OUTD + oo] = vb;

        cur = nxt;
    }
}

// ================= launch =================
extern "C" void kernel_launch(void* const* d_in, const int* in_sizes, int n_in,
                              void* d_out, int out_size) {
    const float* latent = (const float*)d_in[0];
    const float* w_lh   = (const float*)d_in[1];
    const float* b_lh   = (const float*)d_in[2];
    const float* w_lc   = (const float*)d_in[3];
    const float* b_lc   = (const float*)d_in[4];
    const float* w_ih0  = (const float*)d_in[5];
    const float* w_hh0  = (const float*)d_in[6];
    const float* b_ih0  = (const float*)d_in[7];
    const float* b_hh0  = (const float*)d_in[8];
    const float* w_ih1  = (const float*)d_in[9];
    const float* w_hh1  = (const float*)d_in[10];
    const float* b_ih1  = (const float*)d_in[11];
    const float* b_hh1  = (const float*)d_in[12];
    const float* w_out  = (const float*)d_in[13];
    const float* b_out  = (const float*)d_in[14];
    float* out = (float*)d_out;

    tr_w0<<<256, 256>>>(w_hh0);
    tr_w1<<<512, 256>>>(w_ih1, w_hh1);
    tr_wo<<<64, 256>>>(w_out);
    prep_init<<<BATCH, 256>>>(latent, w_lh, b_lh, w_lc, b_lc, w_ih0, b_ih0, b_hh0);
    lstm_main<<<NCTA, 256>>>(b_ih1, b_hh1, b_out, out);
}

// round 8
// speedup vs baseline: 1.0020x; 1.0020x over previous
#include <cuda_runtime.h>

// Problem constants
#define T_STEPS 256
#define HID     256
#define BATCH   1024
#define LATD    128
#define OUTD    64
#define BC      8      // batch rows per CTA
#define NCTA    (BATCH / BC)  // 128

// -------- persistent scratch (no allocations allowed) --------
// transposed, gate-interleaved weights:
//   g_w0t4[k*256 + j] = (Whh0[j][k], Whh0[j+256][k], Whh0[j+512][k], Whh0[j+768][k])
__device__ float4 g_w0t4[256 * 256];          // 1 MB
// layer1 concatenated [Wih1 ; Whh1], rows k=0..511
__device__ float4 g_w1t4[512 * 256];          // 2 MB
__device__ float  g_wot[256 * 64];            // w_out transposed [k][o]
__device__ float  g_gx0[BATCH * 1024];        // latent@Wih0^T + b_ih0 + b_hh0
__device__ float  g_hinit[BATCH * 512];       // [b][layer*256 + j]
__device__ float  g_cinit[BATCH * 512];

// -------- packed f32x2 helpers (sm_103a FFMA2 path) --------
typedef unsigned long long ull;
__device__ __forceinline__ ull pk2(float a, float b) {
    ull r; asm("mov.b64 %0, {%1, %2};" : "=l"(r) : "f"(a), "f"(b)); return r;
}
__device__ __forceinline__ void upk2(ull v, float& a, float& b) {
    asm("mov.b64 {%0, %1}, %2;" : "=f"(a), "=f"(b) : "l"(v));
}
__device__ __forceinline__ ull dup2f(float a) {
    ull r; asm("mov.b64 %0, {%1, %1};" : "=l"(r) : "f"(a)); return r;
}
__device__ __forceinline__ ull fma2(ull a, ull b, ull c) {
    ull d; asm("fma.rn.f32x2 %0, %1, %2, %3;" : "=l"(d) : "l"(a), "l"(b), "l"(c)); return d;
}

__device__ __forceinline__ float sigf(float x) {
    return __fdividef(1.f, 1.f + __expf(-x));
}
__device__ __forceinline__ float tanh_fast(float x) {
    x = fminf(fmaxf(x, -15.f), 15.f);
    float e = __expf(2.f * x);
    return __fdividef(e - 1.f, e + 1.f);
}

// elementwise LSTM cell update for a packed batch pair
__device__ __forceinline__ void lstm_cell(ull gi, ull gf, ull gg, ull go,
                                          ull& cp, float& ha, float& hb) {
    float ia, ib, fa, fb, ga, gb, oa, ob, ca, cb;
    upk2(gi, ia, ib); upk2(gf, fa, fb); upk2(gg, ga, gb); upk2(go, oa, ob);
    upk2(cp, ca, cb);
    float cna = sigf(fa) * ca + sigf(ia) * tanh_fast(ga);
    float cnb = sigf(fb) * cb + sigf(ib) * tanh_fast(gb);
    ha = sigf(oa) * tanh_fast(cna);
    hb = sigf(ob) * tanh_fast(cnb);
    cp = pk2(cna, cnb);
}

// ================= prep kernels =================

__global__ void tr_w0(const float* __restrict__ w_hh0) {
    int idx = blockIdx.x * blockDim.x + threadIdx.x;   // 65536
    int t = idx & 255, k = idx >> 8;
    g_w0t4[k * 256 + t] = make_float4(
        w_hh0[t * 256 + k],         w_hh0[(t + 256) * 256 + k],
        w_hh0[(t + 512) * 256 + k], w_hh0[(t + 768) * 256 + k]);
}

__global__ void tr_w1(const float* __restrict__ w_ih1, const float* __restrict__ w_hh1) {
    int idx = blockIdx.x * blockDim.x + threadIdx.x;   // 131072
    int t = idx & 255, k = idx >> 8;                   // k in 0..511
    const float* src = (k < 256) ? w_ih1 : w_hh1;
    int kk = k & 255;
    g_w1t4[k * 256 + t] = make_float4(
        src[t * 256 + kk],         src[(t + 256) * 256 + kk],
        src[(t + 512) * 256 + kk], src[(t + 768) * 256 + kk]);
}

__global__ void tr_wo(const float* __restrict__ w_out) {
    int idx = blockIdx.x * blockDim.x + threadIdx.x;   // 16384
    int o = idx & 63, k = idx >> 6;
    g_wot[idx] = w_out[o * 256 + k];
}

// per-batch-row init: gx0, h0/c0 for both layers
__global__ void prep_init(const float* __restrict__ latent,
                          const float* __restrict__ w_lh, const float* __restrict__ b_lh,
                          const float* __restrict__ w_lc, const float* __restrict__ b_lc,
                          const float* __restrict__ w_ih0, const float* __restrict__ b_ih0,
                          const float* __restrict__ b_hh0) {
    __shared__ float lat[LATD];
    const int b = blockIdx.x, t = threadIdx.x;
    if (t < LATD) lat[t] = latent[b * LATD + t];
    __syncthreads();

    // gx0 : 4 gate rows per thread
    #pragma unroll
    for (int g = 0; g < 4; g++) {
        int n = t + 256 * g;
        const float4* wr = (const float4*)(w_ih0 + n * LATD);
        float acc = b_ih0[n] + b_hh0[n];
        #pragma unroll 8
        for (int q = 0; q < LATD / 4; q++) {
            float4 w4 = __ldg(wr + q);
            acc += lat[4 * q] * w4.x + lat[4 * q + 1] * w4.y +
                   lat[4 * q + 2] * w4.z + lat[4 * q + 3] * w4.w;
        }
        g_gx0[b * 1024 + n] = acc;
    }
    // h/c init: j2 in {t, t+256}
    #pragma unroll
    for (int half = 0; half < 2; half++) {
        int j2 = t + 256 * half;
        {
            const float4* wr = (const float4*)(w_lh + j2 * LATD);
            float acc = b_lh[j2];
            #pragma unroll 8
            for (int q = 0; q < LATD / 4; q++) {
                float4 w4 = __ldg(wr + q);
                acc += lat[4 * q] * w4.x + lat[4 * q + 1] * w4.y +
                       lat[4 * q + 2] * w4.z + lat[4 * q + 3] * w4.w;
            }
            g_hinit[b * 512 + j2] = acc;
        }
        {
            const float4* wr = (const float4*)(w_lc + j2 * LATD);
            float acc = b_lc[j2];
            #pragma unroll 8
            for (int q = 0; q < LATD / 4; q++) {
                float4 w4 = __ldg(wr + q);
                acc += lat[4 * q] * w4.x + lat[4 * q + 1] * w4.y +
                       lat[4 * q + 2] * w4.z + lat[4 * q + 3] * w4.w;
            }
            g_cinit[b * 512 + j2] = acc;
        }
    }
}

// ================= main persistent kernel =================
// 128 CTAs x 256 threads. CTA owns 8 batch rows, packed as pairs (bp, bp+4).
// Thread t owns hidden unit j=t of both layers (gate rows t, t+256, t+512, t+768).
// SMEM xp[buf][k][bp]: k<256 -> layer0 h, k>=256 -> layer1 h, packed batch pair.
__global__ void __launch_bounds__(256, 1)
lstm_main(const float* __restrict__ b_ih1, const float* __restrict__ b_hh1,
          const float* __restrict__ b_out, float* __restrict__ out) {
    __shared__ ull xp[2][512][4];
    const int t  = threadIdx.x;
    const int bg = blockIdx.x * BC;

    ull c0p[4], c1p[4], gxp[4][4], b1p[4];
    #pragma unroll
    for (int bp = 0; bp < 4; bp++) {
        int b0 = bg + bp, b1 = bg + bp + 4;
        xp[0][t][bp]       = pk2(g_hinit[b0 * 512 + t],       g_hinit[b1 * 512 + t]);
        xp[0][256 + t][bp] = pk2(g_hinit[b0 * 512 + 256 + t], g_hinit[b1 * 512 + 256 + t]);
        c0p[bp] = pk2(g_cinit[b0 * 512 + t],       g_cinit[b1 * 512 + t]);
        c1p[bp] = pk2(g_cinit[b0 * 512 + 256 + t], g_cinit[b1 * 512 + 256 + t]);
        #pragma unroll
        for (int g = 0; g < 4; g++)
            gxp[g][bp] = pk2(g_gx0[b0 * 1024 + t + 256 * g],
                             g_gx0[b1 * 1024 + t + 256 * g]);
    }
    #pragma unroll
    for (int g = 0; g < 4; g++)
        b1p[g] = dup2f(b_ih1[t + 256 * g] + b_hh1[t + 256 * g]);

    const int oo = t & 63;
    const int rr = t >> 6;
    const ull bop = dup2f(b_out[oo]);

    __syncthreads();

    int cur = 0;
    for (int step = 0; step < T_STEPS; step++) {
        const int nxt = cur ^ 1;

        // ---------- layer 0: gates = gx0 + h0 @ Whh0^T ----------
        ull acc[4][4];
        #pragma unroll
        for (int g = 0; g < 4; g++)
            #pragma unroll
            for (int bp = 0; bp < 4; bp++) acc[g][bp] = gxp[g][bp];

        #pragma unroll 8
        for (int k = 0; k < 256; k++) {
            float4 w = __ldg(&g_w0t4[k * 256 + t]);
            ull wx = dup2f(w.x), wy = dup2f(w.y), wz = dup2f(w.z), ww = dup2f(w.w);
            #pragma unroll
            for (int bp = 0; bp < 4; bp++) {
                ull xv = xp[cur][k][bp];
                acc[0][bp] = fma2(xv, wx, acc[0][bp]);
                acc[1][bp] = fma2(xv, wy, acc[1][bp]);
                acc[2][bp] = fma2(xv, wz, acc[2][bp]);
                acc[3][bp] = fma2(xv, ww, acc[3][bp]);
            }
        }
        #pragma unroll
        for (int bp = 0; bp < 4; bp++) {
            float ha, hb;
            lstm_cell(acc[0][bp], acc[1][bp], acc[2][bp], acc[3][bp], c0p[bp], ha, hb);
            xp[nxt][t][bp] = pk2(ha, hb);
        }
        __syncthreads();   // h0_new visible

        // ---------- layer 1: gates = bias1 + h0_new @ Wih1^T + h1 @ Whh1^T ----------
        #pragma unroll
        for (int g = 0; g < 4; g++)
            #pragma unroll
            for (int bp = 0; bp < 4; bp++) acc[g][bp] = b1p[g];

        #pragma unroll 8
        for (int k = 0; k < 256; k++) {
            float4 w = __ldg(&g_w1t4[k * 256 + t]);
            ull wx = dup2f(w.x), wy = dup2f(w.y), wz = dup2f(w.z), ww = dup2f(w.w);
            #pragma unroll
            for (int bp = 0; bp < 4; bp++) {
                ull xv = xp[nxt][k][bp];          // h0_new
                acc[0][bp] = fma2(xv, wx, acc[0][bp]);
                acc[1][bp] = fma2(xv, wy, acc[1][bp]);
                acc[2][bp] = fma2(xv, wz, acc[2][bp]);
                acc[3][bp] = fma2(xv, ww, acc[3][bp]);
            }
        }
        #pragma unroll 8
        for (int k = 0; k < 256; k++) {
            float4 w = __ldg(&g_w1t4[(256 + k) * 256 + t]);
            ull wx = dup2f(w.x), wy = dup2f(w.y), wz = dup2f(w.z), ww = dup2f(w.w);
            #pragma unroll
            for (int bp = 0; bp < 4; bp++) {
                ull xv = xp[cur][256 + k][bp];    // h1_cur
                acc[0][bp] = fma2(xv, wx, acc[0][bp]);
                acc[1][bp] = fma2(xv, wy, acc[1][bp]);
                acc[2][bp] = fma2(xv, wz, acc[2][bp]);
                acc[3][bp] = fma2(xv, ww, acc[3][bp]);
            }
        }
        #pragma unroll
        for (int bp = 0; bp < 4; bp++) {
            float ha, hb;
            lstm_cell(acc[0][bp], acc[1][bp], acc[2][bp], acc[3][bp], c1p[bp], ha, hb);
            xp[nxt][256 + t][bp] = pk2(ha, hb);
        }
        __syncthreads();   // h1_new visible

        // ---------- output projection: out = h1_new @ Wout^T + b_out ----------
        ull oacc = bop;
        #pragma unroll 8
        for (int k = 0; k < 256; k++) {
            float wv = __ldg(&g_wot[k * 64 + oo]);
            oacc = fma2(xp[nxt][256 + k][rr], dup2f(wv), oacc);
        }
        float va, vb;
        upk2(oacc, va, vb);
        out[((bg + rr) * T_STEPS + step) * OUTD + oo]     = va;
        out[((bg + rr + 4) * T_STEPS + step) * OUTD + oo] = vb;

        cur = nxt;
    }
}

// ================= launch =================
extern "C" void kernel_launch(void* const* d_in, const int* in_sizes, int n_in,
                              void* d_out, int out_size) {
    const float* latent = (const float*)d_in[0];
    const float* w_lh   = (const float*)d_in[1];
    const float* b_lh   = (const float*)d_in[2];
    const float* w_lc   = (const float*)d_in[3];
    const float* b_lc   = (const float*)d_in[4];
    const float* w_ih0  = (const float*)d_in[5];
    const float* w_hh0  = (const float*)d_in[6];
    const float* b_ih0  = (const float*)d_in[7];
    const float* b_hh0  = (const float*)d_in[8];
    const float* w_ih1  = (const float*)d_in[9];
    const float* w_hh1  = (const float*)d_in[10];
    const float* b_ih1  = (const float*)d_in[11];
    const float* b_hh1  = (const float*)d_in[12];
    const float* w_out  = (const float*)d_in[13];
    const float* b_out  = (const float*)d_in[14];
    float* out = (float*)d_out;

    tr_w0<<<256, 256>>>(w_hh0);
    tr_w1<<<512, 256>>>(w_ih1, w_hh1);
    tr_wo<<<64, 256>>>(w_out);
    prep_init<<<BATCH, 256>>>(latent, w_lh, b_lh, w_lc, b_lc, w_ih0, b_ih0, b_hh0);
    lstm_main<<<NCTA, 256>>>(b_ih1, b_hh1, b_out, out);
}